// round 10
// baseline (speedup 1.0000x reference)
#include <cuda_runtime.h>
#include <cuda_bf16.h>
#include <cstdint>

#define M_ 16384
#define N_ 3072
#define K_ 1024

// -------- device scratch (allowed: __device__ globals) --------
__device__ float g_qkv[(size_t)M_ * N_];               // 192 MB
__device__ __nv_bfloat16 g_Ah[(size_t)M_ * K_];        // 32 MB  x hi   [M,K]
__device__ __nv_bfloat16 g_Al[(size_t)M_ * K_];        // 32 MB  x lo   [M,K]
__device__ __nv_bfloat16 g_Bh[(size_t)N_ * K_];        // 6 MB   W^T hi [N,K]
__device__ __nv_bfloat16 g_Bl[(size_t)N_ * K_];        // 6 MB   W^T lo [N,K]

// ---------------------------------------------------------------------------
// Pre-kernel 1: split x -> bf16 hi/lo, same [M,K] layout.
// ---------------------------------------------------------------------------
__global__ __launch_bounds__(256) void split_x_kernel(const float* __restrict__ x)
{
    size_t idx = (size_t)blockIdx.x * 256 + threadIdx.x;    // float4 index
    float4 v = ((const float4*)x)[idx];
    __nv_bfloat16 hx = __float2bfloat16(v.x);
    __nv_bfloat16 hy = __float2bfloat16(v.y);
    __nv_bfloat16 hz = __float2bfloat16(v.z);
    __nv_bfloat16 hw = __float2bfloat16(v.w);
    __nv_bfloat16 lx = __float2bfloat16(v.x - __bfloat162float(hx));
    __nv_bfloat16 ly = __float2bfloat16(v.y - __bfloat162float(hy));
    __nv_bfloat16 lz = __float2bfloat16(v.z - __bfloat162float(hz));
    __nv_bfloat16 lw = __float2bfloat16(v.w - __bfloat162float(hw));
    __nv_bfloat162 h01; h01.x = hx; h01.y = hy;
    __nv_bfloat162 h23; h23.x = hz; h23.y = hw;
    __nv_bfloat162 l01; l01.x = lx; l01.y = ly;
    __nv_bfloat162 l23; l23.x = lz; l23.y = lw;
    ((__nv_bfloat162*)g_Ah)[2 * idx]     = h01;
    ((__nv_bfloat162*)g_Ah)[2 * idx + 1] = h23;
    ((__nv_bfloat162*)g_Al)[2 * idx]     = l01;
    ((__nv_bfloat162*)g_Al)[2 * idx + 1] = l23;
}

// ---------------------------------------------------------------------------
// Pre-kernel 2: transpose + split W [K,N] -> g_Bh/g_Bl bf16 [N,K].
// ---------------------------------------------------------------------------
__global__ __launch_bounds__(256) void split_w_kernel(const float* __restrict__ W)
{
    __shared__ float t[32][33];
    const int k0 = blockIdx.x * 32;
    const int n0 = blockIdx.y * 32;
    const int tid = threadIdx.x;
    #pragma unroll
    for (int i = 0; i < 4; i++) {
        int idx = tid + i * 256;
        int r = idx >> 5, c = idx & 31;
        t[r][c] = W[(size_t)(k0 + r) * N_ + n0 + c];
    }
    __syncthreads();
    #pragma unroll
    for (int i = 0; i < 4; i++) {
        int idx = tid + i * 256;
        int r = idx >> 5, c = idx & 31;
        float v = t[c][r];
        __nv_bfloat16 hi = __float2bfloat16(v);
        __nv_bfloat16 lo = __float2bfloat16(v - __bfloat162float(hi));
        size_t o = (size_t)(n0 + r) * K_ + k0 + c;
        g_Bh[o] = hi;
        g_Bl[o] = lo;
    }
}

// ---------------------------------------------------------------------------
// Main GEMM: qkv = x @ W + b via mma.sync.m16n8k16 bf16, 3-pass split.
// CTA tile 128x64, 8 warps (4x2), warp tile 32x32, KC=32, 2-stage cp.async.
// Small warp tile => ~95 regs => TWO CTAs per SM (the R5 occupancy theory,
// now without spills). smem rows padded to 40 bf16 (80B).
// ---------------------------------------------------------------------------
#define KC 32
#define ASTRIDE 40
#define ROWB (ASTRIDE * 2)                   // 80 bytes per smem row
#define A_TILE_B (128 * ROWB)                // 10240
#define B_TILE_B (64 * ROWB)                 // 5120
#define STG_BYTES (2 * A_TILE_B + 2 * B_TILE_B)   // Ah, Al, Bh, Bl = 30720
#define OFF_AL (A_TILE_B)
#define OFF_BH (2 * A_TILE_B)
#define OFF_BL (2 * A_TILE_B + B_TILE_B)
#define SMEM_TOTAL (2 * STG_BYTES)           // 61440

__device__ __forceinline__ uint32_t cvta_smem(const void* p) {
    uint32_t a;
    asm("{ .reg .u64 t; cvta.to.shared.u64 t, %1; cvt.u32.u64 %0, t; }"
        : "=r"(a) : "l"(p));
    return a;
}

#define CP16(dst, src) \
    asm volatile("cp.async.cg.shared.global [%0], [%1], 16;" \
                 :: "r"(dst), "l"(src) : "memory")

#define LDSM4(r, addr) \
    asm volatile("ldmatrix.sync.aligned.m8n8.x4.shared.b16 {%0,%1,%2,%3}, [%4];" \
                 : "=r"((r)[0]), "=r"((r)[1]), "=r"((r)[2]), "=r"((r)[3]) \
                 : "r"(addr))

#define MMA16816(c, a, b0, b1) \
    asm volatile("mma.sync.aligned.m16n8k16.row.col.f32.bf16.bf16.f32 " \
                 "{%0,%1,%2,%3}, {%4,%5,%6,%7}, {%8,%9}, {%0,%1,%2,%3};" \
                 : "+f"((c)[0]), "+f"((c)[1]), "+f"((c)[2]), "+f"((c)[3]) \
                 : "r"((a)[0]), "r"((a)[1]), "r"((a)[2]), "r"((a)[3]), \
                   "r"(b0), "r"(b1))

__global__ __launch_bounds__(256, 2) void gemm_bf16_kernel(const float* __restrict__ bias)
{
    extern __shared__ __align__(128) char smem[];
    const uint32_t sb = cvta_smem(smem);

    const int tid  = threadIdx.x;
    const int wid  = tid >> 5;
    const int lane = tid & 31;
    const int wm   = wid >> 1;          // 0..3 (M, 32 rows each)
    const int wn   = wid & 1;           // 0..1 (N, 32 cols each)
    const int n0 = blockIdx.x * 64;
    const int m0 = blockIdx.y * 128;

    // cp.async coordinates:
    // A: 128 rows x 64B/limb; 2 threads/row, 2 CP16 each.
    const int ar  = tid >> 1;            // 0..127
    const int acb = (tid & 1) * 32;      // byte offset in row payload
    // B: 64 rows x 64B/limb; 4 threads/row, 1 CP16 each.
    const int br  = tid >> 2;            // 0..63
    const int bcb = (tid & 3) * 16;

    float acc[2][4][4];
    #pragma unroll
    for (int i = 0; i < 2; i++)
        #pragma unroll
        for (int j = 0; j < 4; j++)
            #pragma unroll
            for (int q = 0; q < 4; q++) acc[i][j][q] = 0.0f;

    #define LOAD_STAGE(s, c)  do {                                                \
        uint32_t db = sb + (s) * STG_BYTES;                                       \
        int k0 = (c) * KC;                                                        \
        const char* ah = (const char*)(g_Ah + (size_t)(m0 + ar) * K_ + k0) + acb; \
        const char* al = (const char*)(g_Al + (size_t)(m0 + ar) * K_ + k0) + acb; \
        const char* bh = (const char*)(g_Bh + (size_t)(n0 + br) * K_ + k0) + bcb; \
        const char* bl = (const char*)(g_Bl + (size_t)(n0 + br) * K_ + k0) + bcb; \
        uint32_t da = db + ar * ROWB + acb;                                       \
        uint32_t dbb = db + br * ROWB + bcb;                                      \
        CP16(da, ah);                    CP16(da + 16, ah + 16);                  \
        CP16(da + OFF_AL, al);           CP16(da + OFF_AL + 16, al + 16);         \
        CP16(dbb + OFF_BH, bh);                                                   \
        CP16(dbb + OFF_BL, bl);                                                   \
        asm volatile("cp.async.commit_group;" ::: "memory");                      \
    } while (0)

    LOAD_STAGE(0, 0);

    // ldmatrix lane addressing (constant across chunks)
    const int rA = wm * 32 + ((lane >> 3) & 1) * 8 + (lane & 7);
    const int cA = ((lane >> 4) & 1) * 8;                  // + kk*16
    const int rB = wn * 32 + ((lane >> 4) & 1) * 8 + (lane & 7);
    const int cB = ((lane >> 3) & 1) * 8;                  // + kk*16

    const int NCH = K_ / KC;
    for (int c = 0; c < NCH; c++) {
        if (c + 1 < NCH) {
            LOAD_STAGE((c + 1) & 1, c + 1);
            asm volatile("cp.async.wait_group 1;" ::: "memory");
        } else {
            asm volatile("cp.async.wait_group 0;" ::: "memory");
        }
        __syncthreads();

        const uint32_t st = sb + (c & 1) * STG_BYTES;
        #pragma unroll
        for (int kk = 0; kk < 2; kk++) {
            uint32_t a_h[2][4], a_l[2][4], b_h[2][4], b_l[2][4];
            #pragma unroll
            for (int mi = 0; mi < 2; mi++) {
                uint32_t ad = st + (rA + mi * 16) * ROWB + (cA + kk * 16) * 2;
                LDSM4(a_h[mi], ad);
                LDSM4(a_l[mi], ad + OFF_AL);
            }
            #pragma unroll
            for (int ni = 0; ni < 2; ni++) {
                uint32_t bd = st + OFF_BH + (rB + ni * 16) * ROWB + (cB + kk * 16) * 2;
                LDSM4(b_h[ni], bd);
                LDSM4(b_l[ni], bd + B_TILE_B);
            }
            // pass 1: Ah * Bh
            #pragma unroll
            for (int mi = 0; mi < 2; mi++)
                #pragma unroll
                for (int nj = 0; nj < 4; nj++)
                    MMA16816(acc[mi][nj], a_h[mi],
                             b_h[nj >> 1][(nj & 1) * 2], b_h[nj >> 1][(nj & 1) * 2 + 1]);
            // pass 2: Ah * Bl
            #pragma unroll
            for (int mi = 0; mi < 2; mi++)
                #pragma unroll
                for (int nj = 0; nj < 4; nj++)
                    MMA16816(acc[mi][nj], a_h[mi],
                             b_l[nj >> 1][(nj & 1) * 2], b_l[nj >> 1][(nj & 1) * 2 + 1]);
            // pass 3: Al * Bh
            #pragma unroll
            for (int mi = 0; mi < 2; mi++)
                #pragma unroll
                for (int nj = 0; nj < 4; nj++)
                    MMA16816(acc[mi][nj], a_l[mi],
                             b_h[nj >> 1][(nj & 1) * 2], b_h[nj >> 1][(nj & 1) * 2 + 1]);
        }
        __syncthreads();
    }

    // ---- epilogue: bias + store f32 ----
    #pragma unroll
    for (int mi = 0; mi < 2; mi++) {
        #pragma unroll
        for (int nj = 0; nj < 4; nj++) {
            int row = m0 + wm * 32 + mi * 16 + (lane >> 2);
            int col = n0 + wn * 32 + nj * 8 + (lane & 3) * 2;
            float2 bv = *(const float2*)(bias + col);
            float2 v0, v1;
            v0.x = acc[mi][nj][0] + bv.x;
            v0.y = acc[mi][nj][1] + bv.y;
            v1.x = acc[mi][nj][2] + bv.x;
            v1.y = acc[mi][nj][3] + bv.y;
            *(float2*)(g_qkv + (size_t)row * N_ + col)       = v0;
            *(float2*)(g_qkv + (size_t)(row + 8) * N_ + col) = v1;
        }
    }
}

// ---------------------------------------------------------------------------
// Attention kernel: exact R5 version (best measured: 93.2us).
// Padded per-head stride 196 floats; scalar loops, no skew arithmetic.
// ---------------------------------------------------------------------------
#define HSTR 196                         // padded per-head stride (floats)
#define HSTR4 49                         // float4 stride

__global__ __launch_bounds__(256, 4) void attn_kernel(float* __restrict__ out)
{
    __shared__ __align__(16) float qkv[16 * HSTR];   // 12.25 KB
    __shared__ float E[256];
    __shared__ float invden[16];

    const int token = blockIdx.x;
    const int tid   = threadIdx.x;

    // Stage token row (768 float4) into padded layout: 48 float4 per head.
    const float4* row4 = (const float4*)(g_qkv + (size_t)token * N_);
    #pragma unroll
    for (int r = 0; r < 3; r++) {
        int i = tid + r * 256;
        int head = i / 48;
        int w    = i - head * 48;
        ((float4*)qkv)[head * HSTR4 + w] = row4[i];
    }
    __syncthreads();

    // Scores: one (h,g) per thread; plain unrolled dot product.
    const int h = tid >> 4;
    const int g = tid & 15;
    const float* qp = &qkv[h * HSTR];
    const float* kp = &qkv[g * HSTR + 64];
    float s = 0.0f;
    #pragma unroll
    for (int d = 0; d < 64; d++)
        s = fmaf(qp[d], kp[d], s);
    s -= 20.0f;
    E[tid] = (s > 20.0f || s < -20.0f) ? 0.0f : expf(s);
    __syncthreads();

    if (tid < 16) {
        float den = 0.0f;
        #pragma unroll
        for (int gg = 0; gg < 16; gg++) den += E[tid * 16 + gg];
        invden[tid] = 1.0f / den;
    }
    __syncthreads();

    // out[h,d] = (1/den_h) * sum_g E[h,g] * V[g,d]
    float* o = out + (size_t)token * 1024;
    #pragma unroll
    for (int r = 0; r < 4; r++) {
        int idx = tid + r * 256;
        int hh = idx >> 6;
        int d  = idx & 63;
        float a = 0.0f;
        #pragma unroll
        for (int gg = 0; gg < 16; gg++)
            a = fmaf(E[hh * 16 + gg], qkv[gg * HSTR + 128 + d], a);
        o[idx] = a * invden[hh];
    }
}

// ---------------------------------------------------------------------------
extern "C" void kernel_launch(void* const* d_in, const int* in_sizes, int n_in,
                              void* d_out, int out_size)
{
    const float* x = (const float*)d_in[0];
    const float* W = (const float*)d_in[1];
    const float* b = (const float*)d_in[2];
    float* out = (float*)d_out;

    cudaFuncSetAttribute(gemm_bf16_kernel,
                         cudaFuncAttributeMaxDynamicSharedMemorySize, SMEM_TOTAL);

    split_x_kernel<<<(M_ * K_) / (256 * 4), 256>>>(x);
    split_w_kernel<<<dim3(K_ / 32, N_ / 32), 256>>>(W);
    gemm_bf16_kernel<<<dim3(N_ / 64, M_ / 128), 256, SMEM_TOTAL>>>(b);
    attn_kernel<<<M_, 256>>>(out);
}